// round 6
// baseline (speedup 1.0000x reference)
#include <cuda_runtime.h>
#include <math.h>

#define BATCH 8
#define TK    512
#define FDIM  32
#define NTQ   128
#define EDIM  128
#define HDIM  128

typedef unsigned long long u64;

// ---------------- scratch (static device memory; no allocations) ----------------
__device__ float g_q[NTQ * EDIM];
__device__ float g_k[BATCH * TK * EDIM];
__device__ float g_att[BATCH * NTQ * 64];
__device__ float g_gi[BATCH * NTQ * 384];
__device__ float g_hl[BATCH * HDIM];

__device__ __forceinline__ float wsum(float v) {
#pragma unroll
    for (int o = 16; o; o >>= 1) v += __shfl_xor_sync(0xffffffffu, v, o);
    return v;
}
__device__ __forceinline__ float wmax(float v) {
#pragma unroll
    for (int o = 16; o; o >>= 1) v = fmaxf(v, __shfl_xor_sync(0xffffffffu, v, o));
    return v;
}

// packed f32x2 FMA (FFMA2) — 2 MACs per issue slot; PTX-only on sm_103a
__device__ __forceinline__ u64 ffma2(u64 a, u64 b, u64 c) {
    u64 d;
    asm("fma.rn.f32x2 %0, %1, %2, %3;" : "=l"(d) : "l"(a), "l"(b), "l"(c));
    return d;
}
__device__ __forceinline__ u64 fadd2(u64 a, u64 b) {
    u64 d;
    asm("add.rn.f32x2 %0, %1, %2;" : "=l"(d) : "l"(a), "l"(b));
    return d;
}
__device__ __forceinline__ float f2sum(u64 a) {
    float2 v = *(float2*)&a;
    return v.x + v.y;
}
// fast tanh via MUFU.TANH (sm_75+)
__device__ __forceinline__ float tanhapx(float x) {
    float y;
    asm("tanh.approx.f32 %0, %1;" : "=f"(y) : "f"(x));
    return y;
}
// sigmoid(x) = 0.5*tanh(0.5x)+0.5  (1 MUFU + 2 FFMA)
__device__ __forceinline__ float sigapx(float x) {
    return fmaf(tanhapx(0.5f * x), 0.5f, 0.5f);
}

// ---------------------------------------------------------------------------
// Kernel 1: time embedding -> proj -> LN for BOTH q (blocks 0..3) and k (4..131).
// ---------------------------------------------------------------------------
__global__ __launch_bounds__(128) void k_embed(
    const float* __restrict__ times,
    const float* __restrict__ pw, const float* __restrict__ pb,
    const float* __restrict__ lw, const float* __restrict__ lb,
    const float* __restrict__ qW, const float* __restrict__ qbias,
    const float* __restrict__ qg, const float* __restrict__ qbe,
    const float* __restrict__ kW, const float* __restrict__ kbias,
    const float* __restrict__ kg, const float* __restrict__ kbe)
{
    __shared__ float emb[32 * 128];
    __shared__ float pm[32 * 132];
    const int tid = threadIdx.x;
    const bool isQ = blockIdx.x < 4;
    const int r0 = isQ ? blockIdx.x * 32 : (blockIdx.x - 4) * 32;
    float* outp = isQ ? g_q : g_k;
    const float* W     = isQ ? qW : kW;
    const float* bias  = isQ ? qbias : kbias;
    const float* gamma = isQ ? qg : kg;
    const float* beta  = isQ ? qbe : kbe;

    const float lwv = lw[0], lbv = lb[0];
    for (int i = tid; i < 32 * 128; i += 128) {
        int r = i >> 7, e = i & 127;
        float t = isQ ? (float)(r0 + r) * (1.0f / 127.0f) : times[r0 + r];
        float v = (e == 0) ? (t * lwv + lbv) : __sinf(t * pw[e - 1] + pb[e - 1]);
        emb[i] = v;
    }
    __syncthreads();

    u64 w2[64];
    {
        const ulonglong2* wr = (const ulonglong2*)(W + tid * 128);
#pragma unroll
        for (int i = 0; i < 32; i++) { ulonglong2 v = wr[i]; w2[2 * i] = v.x; w2[2 * i + 1] = v.y; }
    }
    const float bv = bias[tid];

    for (int r = 0; r < 32; r++) {
        const ulonglong2* er = (const ulonglong2*)(emb + r * 128);
        u64 a0 = 0, a1 = 0, a2 = 0, a3 = 0;
#pragma unroll
        for (int i = 0; i < 16; i++) {
            ulonglong2 e0 = er[2 * i], e1 = er[2 * i + 1];
            a0 = ffma2(w2[4 * i],     e0.x, a0);
            a1 = ffma2(w2[4 * i + 1], e0.y, a1);
            a2 = ffma2(w2[4 * i + 2], e1.x, a2);
            a3 = ffma2(w2[4 * i + 3], e1.y, a3);
        }
        pm[r * 132 + tid] = bv + f2sum(fadd2(fadd2(a0, a1), fadd2(a2, a3)));
    }
    __syncthreads();

    const int wid = tid >> 5, lane = tid & 31;
    for (int rr = 0; rr < 8; rr++) {
        int r = wid * 8 + rr;
        float v0 = pm[r * 132 + lane];
        float v1 = pm[r * 132 + lane + 32];
        float v2 = pm[r * 132 + lane + 64];
        float v3 = pm[r * 132 + lane + 96];
        float mean = wsum(v0 + v1 + v2 + v3) * (1.0f / 128.0f);
        float d0 = v0 - mean, d1 = v1 - mean, d2 = v2 - mean, d3 = v3 - mean;
        float var = wsum(d0 * d0 + d1 * d1 + d2 * d2 + d3 * d3) * (1.0f / 128.0f);
        float rs = rsqrtf(var + 1e-5f);
        float* orow = outp + (r0 + r) * 128;
        orow[lane]      = d0 * rs * gamma[lane]      + beta[lane];
        orow[lane + 32] = d1 * rs * gamma[lane + 32] + beta[lane + 32];
        orow[lane + 64] = d2 * rs * gamma[lane + 64] + beta[lane + 64];
        orow[lane + 96] = d3 * rs * gamma[lane + 96] + beta[lane + 96];
    }
}

// ---------------------------------------------------------------------------
// Kernel 2: FUSED scores + per-channel masked attention.
// ---------------------------------------------------------------------------
#define SATTN_SMEM ((8 * 128 + 128 * 132 + 8 * 516) * 4)

__global__ __launch_bounds__(512) void k_sattn(
    const float* __restrict__ input, const float* __restrict__ mask)
{
    extern __shared__ float sm[];
    float* sQ = sm;                  // 1024
    float* sK = sQ + 8 * 128;        // 128*132
    float* sE = sK + 128 * 132;      // 8*516

    const int tid = threadIdx.x;
    const int b = blockIdx.x >> 4;
    const int nt0 = (blockIdx.x & 15) * 8;
    const float scale = 0.08838834764831845f;  // 1/sqrt(128)

    if (tid < 256)
        ((float4*)sQ)[tid] = ((const float4*)(g_q + nt0 * 128))[tid];

    const int tl = tid & 127;
    const int ntp = tid >> 7;

    for (int kt = 0; kt < 4; kt++) {
        __syncthreads();
#pragma unroll
        for (int i = 0; i < 8; i++) {
            int idx = tid + i * 512;
            int row = idx >> 5, c4 = idx & 31;
            float4 v = ((const float4*)(g_k + ((b * TK) + kt * 128 + row) * 128))[c4];
            *(float4*)(sK + row * 132 + c4 * 4) = v;
        }
        __syncthreads();

        const ulonglong2* kr = (const ulonglong2*)(sK + tl * 132);
        const ulonglong2* q0 = (const ulonglong2*)(sQ + (ntp * 2) * 128);
        const ulonglong2* q1 = q0 + 32;
        u64 a00 = 0, a01 = 0, a10 = 0, a11 = 0;
#pragma unroll
        for (int i = 0; i < 32; i++) {
            ulonglong2 kv = kr[i];
            ulonglong2 qa = q0[i];
            ulonglong2 qb = q1[i];
            a00 = ffma2(qa.x, kv.x, a00);
            a01 = ffma2(qa.y, kv.y, a01);
            a10 = ffma2(qb.x, kv.x, a10);
            a11 = ffma2(qb.y, kv.y, a11);
        }
        int t = kt * 128 + tl;
        sE[(ntp * 2) * 516 + t]     = f2sum(fadd2(a00, a01)) * scale;
        sE[(ntp * 2 + 1) * 516 + t] = f2sum(fadd2(a10, a11)) * scale;
    }
    __syncthreads();

    {
        int wid = tid >> 5, lane = tid & 31;
        if (wid < 8) {
            float* erow = sE + wid * 516;
            float mx = -1e30f;
#pragma unroll
            for (int k = 0; k < 16; k++) mx = fmaxf(mx, erow[lane + 32 * k]);
            mx = wmax(mx);
#pragma unroll
            for (int k = 0; k < 16; k++) {
                int t = lane + 32 * k;
                erow[t] = __expf(erow[t] - mx);
            }
        }
    }
    __syncthreads();

    const int c = tid >> 4;
    const int nt = (tid >> 1) & 7;
    const int half = tid & 1;
    const float4* mrow = (const float4*)(mask  + (b * FDIM + c) * TK + half * 256);
    const float4* xrow = (const float4*)(input + (b * FDIM + c) * TK + half * 256);
    const float* erow = sE + nt * 516 + half * 256;

    float den = 0.f, num = 0.f;
#pragma unroll 4
    for (int t4 = 0; t4 < 64; t4++) {
        float4 e4 = *(const float4*)(erow + 4 * t4);
        float4 mk = mrow[t4];
        float4 xv = xrow[t4];
        float m0 = (mk.x == 0.f) ? 1.f : 0.f;
        float m1 = (mk.y == 0.f) ? 1.f : 0.f;
        float m2 = (mk.z == 0.f) ? 1.f : 0.f;
        float m3 = (mk.w == 0.f) ? 1.f : 0.f;
        den += e4.x * m0 + e4.y * m1 + e4.z * m2 + e4.w * m3;
        num += e4.x * m0 * xv.x + e4.y * m1 * xv.y + e4.z * m2 * xv.z + e4.w * m3 * xv.w;
    }
    den += __shfl_xor_sync(0xffffffffu, den, 1);
    num += __shfl_xor_sync(0xffffffffu, num, 1);
    if (half == 0) {
        float ax = (den > 0.f) ? (num / den) : 0.f;
        float am = (den > 0.f) ? 1.f : 0.f;
        float* arow = g_att + (b * NTQ + nt0 + nt) * 64;
        arow[c]      = ax;
        arow[c + 32] = am;
    }
}

// ---------------------------------------------------------------------------
// Kernel 3: attn LN -> out proj -> LN -> gi = out @ Wih^T + bih
// ---------------------------------------------------------------------------
__global__ __launch_bounds__(384, 1) void k_post(
    const float* __restrict__ attn_g, const float* __restrict__ attn_b,
    const float* __restrict__ out_w,  const float* __restrict__ out_b,
    const float* __restrict__ out_g,  const float* __restrict__ out_be,
    const float* __restrict__ wih,    const float* __restrict__ bih)
{
    __shared__ float satt[16 * 64];
    __shared__ float x2[16 * 64];
    __shared__ float ov[16 * 128];
    const int tid = threadIdx.x;
    const int b = blockIdx.x >> 3;
    const int nt0 = (blockIdx.x & 7) * 16;
    const int wid = tid >> 5, lane = tid & 31;

    for (int i = tid; i < 1024; i += 384)
        satt[i] = g_att[(b * NTQ + nt0) * 64 + i];
    __syncthreads();

    if (wid < 8) {
        for (int rr = 0; rr < 2; rr++) {
            int r = wid * 2 + rr;
            float v0 = satt[r * 64 + lane];
            float v1 = satt[r * 64 + lane + 32];
            float mean = wsum(v0 + v1) * (1.0f / 64.0f);
            float d0 = v0 - mean, d1 = v1 - mean;
            float var = wsum(d0 * d0 + d1 * d1) * (1.0f / 64.0f);
            float rs = rsqrtf(var + 1e-5f);
            x2[r * 64 + lane]      = d0 * rs * attn_g[lane]      + attn_b[lane];
            x2[r * 64 + lane + 32] = d1 * rs * attn_g[lane + 32] + attn_b[lane + 32];
        }
    }
    __syncthreads();

    if (tid < 256) {
        int h = tid & 127, half = tid >> 7;
        u64 wo2[32];
        const ulonglong2* wrow = (const ulonglong2*)(out_w + h * 64);
#pragma unroll
        for (int i = 0; i < 16; i++) { ulonglong2 v = wrow[i]; wo2[2 * i] = v.x; wo2[2 * i + 1] = v.y; }
        float ob = out_b[h];
        for (int rr = 0; rr < 8; rr++) {
            int r = half * 8 + rr;
            const ulonglong2* xr = (const ulonglong2*)(x2 + r * 64);
            u64 a0 = 0, a1 = 0;
#pragma unroll
            for (int i = 0; i < 16; i++) {
                ulonglong2 xv = xr[i];
                a0 = ffma2(wo2[2 * i],     xv.x, a0);
                a1 = ffma2(wo2[2 * i + 1], xv.y, a1);
            }
            ov[r * 128 + h] = ob + f2sum(fadd2(a0, a1));
        }
    }
    __syncthreads();

    if (wid < 8) {
        for (int rr = 0; rr < 2; rr++) {
            int r = wid * 2 + rr;
            float v0 = ov[r * 128 + lane];
            float v1 = ov[r * 128 + lane + 32];
            float v2 = ov[r * 128 + lane + 64];
            float v3 = ov[r * 128 + lane + 96];
            float mean = wsum(v0 + v1 + v2 + v3) * (1.0f / 128.0f);
            float d0 = v0 - mean, d1 = v1 - mean, d2 = v2 - mean, d3 = v3 - mean;
            float var = wsum(d0 * d0 + d1 * d1 + d2 * d2 + d3 * d3) * (1.0f / 128.0f);
            float rs = rsqrtf(var + 1e-5f);
            ov[r * 128 + lane]      = d0 * rs * out_g[lane]      + out_be[lane];
            ov[r * 128 + lane + 32] = d1 * rs * out_g[lane + 32] + out_be[lane + 32];
            ov[r * 128 + lane + 64] = d2 * rs * out_g[lane + 64] + out_be[lane + 64];
            ov[r * 128 + lane + 96] = d3 * rs * out_g[lane + 96] + out_be[lane + 96];
        }
    }
    __syncthreads();

    {
        u64 w2[64];
        const ulonglong2* wrow = (const ulonglong2*)(wih + tid * 128);
#pragma unroll
        for (int i = 0; i < 32; i++) { ulonglong2 v = wrow[i]; w2[2 * i] = v.x; w2[2 * i + 1] = v.y; }
        float bj = bih[tid];
        for (int r = 0; r < 16; r++) {
            const ulonglong2* h2 = (const ulonglong2*)(ov + r * 128);
            u64 a0 = 0, a1 = 0, a2 = 0, a3 = 0;
#pragma unroll
            for (int i = 0; i < 16; i++) {
                ulonglong2 h0 = h2[2 * i], h1 = h2[2 * i + 1];
                a0 = ffma2(w2[4 * i],     h0.x, a0);
                a1 = ffma2(w2[4 * i + 1], h0.y, a1);
                a2 = ffma2(w2[4 * i + 2], h1.x, a2);
                a3 = ffma2(w2[4 * i + 3], h1.y, a3);
            }
            g_gi[(b * NTQ + nt0 + r) * 384 + tid] =
                bj + f2sum(fadd2(fadd2(a0, a1), fadd2(a2, a3)));
        }
    }
}

// ---------------------------------------------------------------------------
// Kernel 4: GRU recurrence, 8 blocks (1/batch), 768 threads.
// Lane pair (even,odd) splits each output's 128-dot into two 64-halves;
// h stored twice (words 0..63 and 80..143) so the pair's broadcast reads
// hit disjoint banks. Combine via shfl_xor(1). Gates on warps 0..3.
// ---------------------------------------------------------------------------
__global__ __launch_bounds__(768, 1) void k_gru(
    const float* __restrict__ whh, const float* __restrict__ bhh)
{
    __shared__ float sg[144 + 384 + 128 + 128];
    float* sh0 = sg;          // h[0..63]   at words 0..63
    float* shB = sg + 80;     // h[64..127] at words 80..143 (bank offset 16)
    float* s1  = sg + 144;    // 384: acc+gi for all outputs
    float* sn  = sg + 528;    // 128: gh for n gate
    float* sgn = sg + 656;    // 128: gi for n gate

    const int tid = threadIdx.x;
    const int j = tid >> 1;          // output index 0..383
    const int half = tid & 1;        // which 64-half of h
    const int b = blockIdx.x;

    u64 w2[32];
    {
        const ulonglong2* wr = (const ulonglong2*)(whh + j * 128 + half * 64);
#pragma unroll
        for (int i = 0; i < 16; i++) { ulonglong2 v = wr[i]; w2[2 * i] = v.x; w2[2 * i + 1] = v.y; }
    }
    const float bj = bhh[j];
    if (tid < 64) sh0[tid] = 0.f;
    else if (tid < 128) shB[tid - 64] = 0.f;
    float giv = g_gi[(b * NTQ) * 384 + j];
    __syncthreads();

    const ulonglong2* h2 = (const ulonglong2*)(half ? shB : sh0);

    for (int t = 0; t < NTQ; t++) {
        u64 a0 = 0, a1 = 0;
#pragma unroll
        for (int i = 0; i < 16; i++) {
            ulonglong2 hv = h2[i];
            a0 = ffma2(w2[2 * i],     hv.x, a0);
            a1 = ffma2(w2[2 * i + 1], hv.y, a1);
        }
        float part = f2sum(fadd2(a0, a1));
        part += __shfl_xor_sync(0xffffffffu, part, 1);
        float acc = part + bj;
        float cur = giv;
        if (t + 1 < NTQ) giv = g_gi[(b * NTQ + t + 1) * 384 + j];  // prefetch
        if (!half) {
            s1[j] = acc + cur;
            if (j >= 256) { sn[j - 256] = acc; sgn[j - 256] = cur; }
        }
        __syncthreads();
        if (tid < 128) {
            float r = sigapx(s1[tid]);
            float z = sigapx(s1[tid + 128]);
            float hv = (tid < 64) ? sh0[tid] : shB[tid - 64];
            float n = tanhapx(fmaf(r, sn[tid], sgn[tid]));
            float nh = fmaf(z, hv - n, n);
            if (tid < 64) sh0[tid] = nh; else shB[tid - 64] = nh;
        }
        __syncthreads();
    }
    if (tid < 128)
        g_hl[b * 128 + tid] = (tid < 64) ? sh0[tid] : shB[tid - 64];
}

// ---------------------------------------------------------------------------
// Kernel 5: classifier MLP -> logits (B, 2)
// ---------------------------------------------------------------------------
__global__ __launch_bounds__(128) void k_cls(
    const float* __restrict__ c1w, const float* __restrict__ c1b,
    const float* __restrict__ c2w, const float* __restrict__ c2b,
    const float* __restrict__ c3w, const float* __restrict__ c3b,
    float* __restrict__ out)
{
    __shared__ float a[128];
    __shared__ float bb[128];
    const int tid = threadIdx.x;
    const int b = blockIdx.x;

    a[tid] = g_hl[b * 128 + tid];
    __syncthreads();
    {
        float acc = c1b[tid];
        const float4* wr = (const float4*)(c1w + tid * 128);
        const float4* h4 = (const float4*)a;
#pragma unroll
        for (int i = 0; i < 32; i++) {
            float4 wv = wr[i]; float4 hv = h4[i];
            acc += hv.x * wv.x + hv.y * wv.y + hv.z * wv.z + hv.w * wv.w;
        }
        bb[tid] = fmaxf(acc, 0.f);
    }
    __syncthreads();
    {
        float acc = c2b[tid];
        const float4* wr = (const float4*)(c2w + tid * 128);
        const float4* h4 = (const float4*)bb;
#pragma unroll
        for (int i = 0; i < 32; i++) {
            float4 wv = wr[i]; float4 hv = h4[i];
            acc += hv.x * wv.x + hv.y * wv.y + hv.z * wv.z + hv.w * wv.w;
        }
        a[tid] = fmaxf(acc, 0.f);
    }
    __syncthreads();
    if (tid < 32) {
        for (int s = 0; s < 2; s++) {
            float p = 0.f;
#pragma unroll
            for (int k = 0; k < 4; k++)
                p += a[tid + 32 * k] * c3w[s * 128 + tid + 32 * k];
            p = wsum(p);
            if (tid == 0) out[b * 2 + s] = p + c3b[s];
        }
    }
}

// ---------------------------------------------------------------------------
extern "C" void kernel_launch(void* const* d_in, const int* in_sizes, int n_in,
                              void* d_out, int out_size)
{
    const float* input      = (const float*)d_in[0];
    const float* mask       = (const float*)d_in[1];
    const float* timesteps  = (const float*)d_in[2];
    const float* periodic_w = (const float*)d_in[3];
    const float* periodic_b = (const float*)d_in[4];
    const float* lin_w      = (const float*)d_in[5];
    const float* lin_b      = (const float*)d_in[6];
    const float* q_w  = (const float*)d_in[7];
    const float* q_b  = (const float*)d_in[8];
    const float* q_g  = (const float*)d_in[9];
    const float* q_be = (const float*)d_in[10];
    const float* k_w  = (const float*)d_in[11];
    const float* k_b  = (const float*)d_in[12];
    const float* k_g  = (const float*)d_in[13];
    const float* k_be = (const float*)d_in[14];
    const float* attn_g = (const float*)d_in[15];
    const float* attn_b = (const float*)d_in[16];
    const float* out_w  = (const float*)d_in[17];
    const float* out_b  = (const float*)d_in[18];
    const float* out_g  = (const float*)d_in[19];
    const float* out_be = (const float*)d_in[20];
    const float* gru_wih = (const float*)d_in[21];
    const float* gru_whh = (const float*)d_in[22];
    const float* gru_bih = (const float*)d_in[23];
    const float* gru_bhh = (const float*)d_in[24];
    const float* c1_w = (const float*)d_in[25];
    const float* c1_b = (const float*)d_in[26];
    const float* c2_w = (const float*)d_in[27];
    const float* c2_b = (const float*)d_in[28];
    const float* c3_w = (const float*)d_in[29];
    const float* c3_b = (const float*)d_in[30];
    float* out = (float*)d_out;

    static bool attr_set = false;
    if (!attr_set) {
        cudaFuncSetAttribute(k_sattn, cudaFuncAttributeMaxDynamicSharedMemorySize, SATTN_SMEM);
        attr_set = true;
    }

    k_embed<<<132, 128>>>(timesteps, periodic_w, periodic_b, lin_w, lin_b,
                          q_w, q_b, q_g, q_be, k_w, k_b, k_g, k_be);
    k_sattn<<<128, 512, SATTN_SMEM>>>(input, mask);
    k_post<<<64, 384>>>(attn_g, attn_b, out_w, out_b, out_g, out_be,
                        gru_wih, gru_bih);
    k_gru<<<8, 768>>>(gru_whh, gru_bhh);
    k_cls<<<8, 128>>>(c1_w, c1_b, c2_w, c2_b, c3_w, c3_b, out);
    (void)in_sizes; (void)n_in; (void)out_size;
}

// round 7
// speedup vs baseline: 1.3053x; 1.3053x over previous
#include <cuda_runtime.h>
#include <math.h>

#define BATCH 8
#define TK    512
#define FDIM  32
#define NTQ   128
#define EDIM  128
#define HDIM  128

typedef unsigned long long u64;

// ---------------- scratch (static device memory; no allocations) ----------------
__device__ float g_q[NTQ * EDIM];
__device__ float g_k[BATCH * TK * EDIM];
__device__ float g_att[BATCH * NTQ * 64];
__device__ float g_gi[BATCH * NTQ * 384];
__device__ float g_hl[BATCH * HDIM];

__device__ __forceinline__ float wsum(float v) {
#pragma unroll
    for (int o = 16; o; o >>= 1) v += __shfl_xor_sync(0xffffffffu, v, o);
    return v;
}
__device__ __forceinline__ float wmax(float v) {
#pragma unroll
    for (int o = 16; o; o >>= 1) v = fmaxf(v, __shfl_xor_sync(0xffffffffu, v, o));
    return v;
}

// packed f32x2 FMA (FFMA2) — 2 MACs per issue slot; PTX-only on sm_103a
__device__ __forceinline__ u64 ffma2(u64 a, u64 b, u64 c) {
    u64 d;
    asm("fma.rn.f32x2 %0, %1, %2, %3;" : "=l"(d) : "l"(a), "l"(b), "l"(c));
    return d;
}
__device__ __forceinline__ u64 fadd2(u64 a, u64 b) {
    u64 d;
    asm("add.rn.f32x2 %0, %1, %2;" : "=l"(d) : "l"(a), "l"(b));
    return d;
}
__device__ __forceinline__ float f2sum(u64 a) {
    float2 v = *(float2*)&a;
    return v.x + v.y;
}
// fast tanh via MUFU.TANH (sm_75+)
__device__ __forceinline__ float tanhapx(float x) {
    float y;
    asm("tanh.approx.f32 %0, %1;" : "=f"(y) : "f"(x));
    return y;
}
// sigmoid(x) = 0.5*tanh(0.5x)+0.5  (1 MUFU + 2 FFMA)
__device__ __forceinline__ float sigapx(float x) {
    return fmaf(tanhapx(0.5f * x), 0.5f, 0.5f);
}

// ---------------------------------------------------------------------------
// Kernel 1: time embedding -> proj -> LN for BOTH q (blocks 0..3) and k (4..131).
// ---------------------------------------------------------------------------
__global__ __launch_bounds__(128) void k_embed(
    const float* __restrict__ times,
    const float* __restrict__ pw, const float* __restrict__ pb,
    const float* __restrict__ lw, const float* __restrict__ lb,
    const float* __restrict__ qW, const float* __restrict__ qbias,
    const float* __restrict__ qg, const float* __restrict__ qbe,
    const float* __restrict__ kW, const float* __restrict__ kbias,
    const float* __restrict__ kg, const float* __restrict__ kbe)
{
    __shared__ float emb[32 * 128];
    __shared__ float pm[32 * 132];
    const int tid = threadIdx.x;
    const bool isQ = blockIdx.x < 4;
    const int r0 = isQ ? blockIdx.x * 32 : (blockIdx.x - 4) * 32;
    float* outp = isQ ? g_q : g_k;
    const float* W     = isQ ? qW : kW;
    const float* bias  = isQ ? qbias : kbias;
    const float* gamma = isQ ? qg : kg;
    const float* beta  = isQ ? qbe : kbe;

    const float lwv = lw[0], lbv = lb[0];
    for (int i = tid; i < 32 * 128; i += 128) {
        int r = i >> 7, e = i & 127;
        float t = isQ ? (float)(r0 + r) * (1.0f / 127.0f) : times[r0 + r];
        float v = (e == 0) ? (t * lwv + lbv) : __sinf(t * pw[e - 1] + pb[e - 1]);
        emb[i] = v;
    }
    __syncthreads();

    u64 w2[64];
    {
        const ulonglong2* wr = (const ulonglong2*)(W + tid * 128);
#pragma unroll
        for (int i = 0; i < 32; i++) { ulonglong2 v = wr[i]; w2[2 * i] = v.x; w2[2 * i + 1] = v.y; }
    }
    const float bv = bias[tid];

    for (int r = 0; r < 32; r++) {
        const ulonglong2* er = (const ulonglong2*)(emb + r * 128);
        u64 a0 = 0, a1 = 0, a2 = 0, a3 = 0;
#pragma unroll
        for (int i = 0; i < 16; i++) {
            ulonglong2 e0 = er[2 * i], e1 = er[2 * i + 1];
            a0 = ffma2(w2[4 * i],     e0.x, a0);
            a1 = ffma2(w2[4 * i + 1], e0.y, a1);
            a2 = ffma2(w2[4 * i + 2], e1.x, a2);
            a3 = ffma2(w2[4 * i + 3], e1.y, a3);
        }
        pm[r * 132 + tid] = bv + f2sum(fadd2(fadd2(a0, a1), fadd2(a2, a3)));
    }
    __syncthreads();

    const int wid = tid >> 5, lane = tid & 31;
    for (int rr = 0; rr < 8; rr++) {
        int r = wid * 8 + rr;
        float v0 = pm[r * 132 + lane];
        float v1 = pm[r * 132 + lane + 32];
        float v2 = pm[r * 132 + lane + 64];
        float v3 = pm[r * 132 + lane + 96];
        float mean = wsum(v0 + v1 + v2 + v3) * (1.0f / 128.0f);
        float d0 = v0 - mean, d1 = v1 - mean, d2 = v2 - mean, d3 = v3 - mean;
        float var = wsum(d0 * d0 + d1 * d1 + d2 * d2 + d3 * d3) * (1.0f / 128.0f);
        float rs = rsqrtf(var + 1e-5f);
        float* orow = outp + (r0 + r) * 128;
        orow[lane]      = d0 * rs * gamma[lane]      + beta[lane];
        orow[lane + 32] = d1 * rs * gamma[lane + 32] + beta[lane + 32];
        orow[lane + 64] = d2 * rs * gamma[lane + 64] + beta[lane + 64];
        orow[lane + 96] = d3 * rs * gamma[lane + 96] + beta[lane + 96];
    }
}

// ---------------------------------------------------------------------------
// Kernel 2: FUSED scores + per-channel masked attention.
// ---------------------------------------------------------------------------
#define SATTN_SMEM ((8 * 128 + 128 * 132 + 8 * 516) * 4)

__global__ __launch_bounds__(512) void k_sattn(
    const float* __restrict__ input, const float* __restrict__ mask)
{
    extern __shared__ float sm[];
    float* sQ = sm;                  // 1024
    float* sK = sQ + 8 * 128;        // 128*132
    float* sE = sK + 128 * 132;      // 8*516

    const int tid = threadIdx.x;
    const int b = blockIdx.x >> 4;
    const int nt0 = (blockIdx.x & 15) * 8;
    const float scale = 0.08838834764831845f;  // 1/sqrt(128)

    if (tid < 256)
        ((float4*)sQ)[tid] = ((const float4*)(g_q + nt0 * 128))[tid];

    const int tl = tid & 127;
    const int ntp = tid >> 7;

    for (int kt = 0; kt < 4; kt++) {
        __syncthreads();
#pragma unroll
        for (int i = 0; i < 8; i++) {
            int idx = tid + i * 512;
            int row = idx >> 5, c4 = idx & 31;
            float4 v = ((const float4*)(g_k + ((b * TK) + kt * 128 + row) * 128))[c4];
            *(float4*)(sK + row * 132 + c4 * 4) = v;
        }
        __syncthreads();

        const ulonglong2* kr = (const ulonglong2*)(sK + tl * 132);
        const ulonglong2* q0 = (const ulonglong2*)(sQ + (ntp * 2) * 128);
        const ulonglong2* q1 = q0 + 32;
        u64 a00 = 0, a01 = 0, a10 = 0, a11 = 0;
#pragma unroll
        for (int i = 0; i < 32; i++) {
            ulonglong2 kv = kr[i];
            ulonglong2 qa = q0[i];
            ulonglong2 qb = q1[i];
            a00 = ffma2(qa.x, kv.x, a00);
            a01 = ffma2(qa.y, kv.y, a01);
            a10 = ffma2(qb.x, kv.x, a10);
            a11 = ffma2(qb.y, kv.y, a11);
        }
        int t = kt * 128 + tl;
        sE[(ntp * 2) * 516 + t]     = f2sum(fadd2(a00, a01)) * scale;
        sE[(ntp * 2 + 1) * 516 + t] = f2sum(fadd2(a10, a11)) * scale;
    }
    __syncthreads();

    {
        int wid = tid >> 5, lane = tid & 31;
        if (wid < 8) {
            float* erow = sE + wid * 516;
            float mx = -1e30f;
#pragma unroll
            for (int k = 0; k < 16; k++) mx = fmaxf(mx, erow[lane + 32 * k]);
            mx = wmax(mx);
#pragma unroll
            for (int k = 0; k < 16; k++) {
                int t = lane + 32 * k;
                erow[t] = __expf(erow[t] - mx);
            }
        }
    }
    __syncthreads();

    const int c = tid >> 4;
    const int nt = (tid >> 1) & 7;
    const int half = tid & 1;
    const float4* mrow = (const float4*)(mask  + (b * FDIM + c) * TK + half * 256);
    const float4* xrow = (const float4*)(input + (b * FDIM + c) * TK + half * 256);
    const float* erow = sE + nt * 516 + half * 256;

    float den = 0.f, num = 0.f;
#pragma unroll 4
    for (int t4 = 0; t4 < 64; t4++) {
        float4 e4 = *(const float4*)(erow + 4 * t4);
        float4 mk = mrow[t4];
        float4 xv = xrow[t4];
        float m0 = (mk.x == 0.f) ? 1.f : 0.f;
        float m1 = (mk.y == 0.f) ? 1.f : 0.f;
        float m2 = (mk.z == 0.f) ? 1.f : 0.f;
        float m3 = (mk.w == 0.f) ? 1.f : 0.f;
        den += e4.x * m0 + e4.y * m1 + e4.z * m2 + e4.w * m3;
        num += e4.x * m0 * xv.x + e4.y * m1 * xv.y + e4.z * m2 * xv.z + e4.w * m3 * xv.w;
    }
    den += __shfl_xor_sync(0xffffffffu, den, 1);
    num += __shfl_xor_sync(0xffffffffu, num, 1);
    if (half == 0) {
        float ax = (den > 0.f) ? (num / den) : 0.f;
        float am = (den > 0.f) ? 1.f : 0.f;
        float* arow = g_att + (b * NTQ + nt0 + nt) * 64;
        arow[c]      = ax;
        arow[c + 32] = am;
    }
}

// ---------------------------------------------------------------------------
// Kernel 3: attn LN -> out proj -> LN -> gi = out @ Wih^T + bih
// ---------------------------------------------------------------------------
__global__ __launch_bounds__(384, 1) void k_post(
    const float* __restrict__ attn_g, const float* __restrict__ attn_b,
    const float* __restrict__ out_w,  const float* __restrict__ out_b,
    const float* __restrict__ out_g,  const float* __restrict__ out_be,
    const float* __restrict__ wih,    const float* __restrict__ bih)
{
    __shared__ float satt[16 * 64];
    __shared__ float x2[16 * 64];
    __shared__ float ov[16 * 128];
    const int tid = threadIdx.x;
    const int b = blockIdx.x >> 3;
    const int nt0 = (blockIdx.x & 7) * 16;
    const int wid = tid >> 5, lane = tid & 31;

    for (int i = tid; i < 1024; i += 384)
        satt[i] = g_att[(b * NTQ + nt0) * 64 + i];
    __syncthreads();

    if (wid < 8) {
        for (int rr = 0; rr < 2; rr++) {
            int r = wid * 2 + rr;
            float v0 = satt[r * 64 + lane];
            float v1 = satt[r * 64 + lane + 32];
            float mean = wsum(v0 + v1) * (1.0f / 64.0f);
            float d0 = v0 - mean, d1 = v1 - mean;
            float var = wsum(d0 * d0 + d1 * d1) * (1.0f / 64.0f);
            float rs = rsqrtf(var + 1e-5f);
            x2[r * 64 + lane]      = d0 * rs * attn_g[lane]      + attn_b[lane];
            x2[r * 64 + lane + 32] = d1 * rs * attn_g[lane + 32] + attn_b[lane + 32];
        }
    }
    __syncthreads();

    if (tid < 256) {
        int h = tid & 127, half = tid >> 7;
        u64 wo2[32];
        const ulonglong2* wrow = (const ulonglong2*)(out_w + h * 64);
#pragma unroll
        for (int i = 0; i < 16; i++) { ulonglong2 v = wrow[i]; wo2[2 * i] = v.x; wo2[2 * i + 1] = v.y; }
        float ob = out_b[h];
        for (int rr = 0; rr < 8; rr++) {
            int r = half * 8 + rr;
            const ulonglong2* xr = (const ulonglong2*)(x2 + r * 64);
            u64 a0 = 0, a1 = 0;
#pragma unroll
            for (int i = 0; i < 16; i++) {
                ulonglong2 xv = xr[i];
                a0 = ffma2(wo2[2 * i],     xv.x, a0);
                a1 = ffma2(wo2[2 * i + 1], xv.y, a1);
            }
            ov[r * 128 + h] = ob + f2sum(fadd2(a0, a1));
        }
    }
    __syncthreads();

    if (wid < 8) {
        for (int rr = 0; rr < 2; rr++) {
            int r = wid * 2 + rr;
            float v0 = ov[r * 128 + lane];
            float v1 = ov[r * 128 + lane + 32];
            float v2 = ov[r * 128 + lane + 64];
            float v3 = ov[r * 128 + lane + 96];
            float mean = wsum(v0 + v1 + v2 + v3) * (1.0f / 128.0f);
            float d0 = v0 - mean, d1 = v1 - mean, d2 = v2 - mean, d3 = v3 - mean;
            float var = wsum(d0 * d0 + d1 * d1 + d2 * d2 + d3 * d3) * (1.0f / 128.0f);
            float rs = rsqrtf(var + 1e-5f);
            ov[r * 128 + lane]      = d0 * rs * out_g[lane]      + out_be[lane];
            ov[r * 128 + lane + 32] = d1 * rs * out_g[lane + 32] + out_be[lane + 32];
            ov[r * 128 + lane + 64] = d2 * rs * out_g[lane + 64] + out_be[lane + 64];
            ov[r * 128 + lane + 96] = d3 * rs * out_g[lane + 96] + out_be[lane + 96];
        }
    }
    __syncthreads();

    {
        u64 w2[64];
        const ulonglong2* wrow = (const ulonglong2*)(wih + tid * 128);
#pragma unroll
        for (int i = 0; i < 32; i++) { ulonglong2 v = wrow[i]; w2[2 * i] = v.x; w2[2 * i + 1] = v.y; }
        float bj = bih[tid];
        for (int r = 0; r < 16; r++) {
            const ulonglong2* h2 = (const ulonglong2*)(ov + r * 128);
            u64 a0 = 0, a1 = 0, a2 = 0, a3 = 0;
#pragma unroll
            for (int i = 0; i < 16; i++) {
                ulonglong2 h0 = h2[2 * i], h1 = h2[2 * i + 1];
                a0 = ffma2(w2[4 * i],     h0.x, a0);
                a1 = ffma2(w2[4 * i + 1], h0.y, a1);
                a2 = ffma2(w2[4 * i + 2], h1.x, a2);
                a3 = ffma2(w2[4 * i + 3], h1.y, a3);
            }
            g_gi[(b * NTQ + nt0 + r) * 384 + tid] =
                bj + f2sum(fadd2(fadd2(a0, a1), fadd2(a2, a3)));
        }
    }
}

// ---------------------------------------------------------------------------
// Kernel 4: GRU recurrence, 8 blocks (1/batch), 256 threads.
// Lane pair (even=low half, odd=high half) computes half-dots of ALL THREE
// gate rows (r, z, n) for output j = tid>>1. Combine with 3 shfl_xor(1);
// even lane computes gates and writes h. Double-buffered h (bank-offset
// upper half) -> ONE __syncthreads per step. h_old kept in register.
// ---------------------------------------------------------------------------
__global__ __launch_bounds__(256, 1) void k_gru(
    const float* __restrict__ whh, const float* __restrict__ bhh)
{
    __shared__ float sbuf[2][132];   // [buf][ 0..63 = h[0..63], 68..131 = h[64..127] ]
    const int tid = threadIdx.x;
    const int j  = tid >> 1;         // output index 0..127
    const int hf = tid & 1;          // which 64-half of h / weight columns
    const int b = blockIdx.x;

    u64 wr[32], wz[32], wn[32];
    {
        const ulonglong2* p = (const ulonglong2*)(whh + j * 128 + hf * 64);
#pragma unroll
        for (int i = 0; i < 16; i++) { ulonglong2 v = p[i]; wr[2 * i] = v.x; wr[2 * i + 1] = v.y; }
        p = (const ulonglong2*)(whh + (j + 128) * 128 + hf * 64);
#pragma unroll
        for (int i = 0; i < 16; i++) { ulonglong2 v = p[i]; wz[2 * i] = v.x; wz[2 * i + 1] = v.y; }
        p = (const ulonglong2*)(whh + (j + 256) * 128 + hf * 64);
#pragma unroll
        for (int i = 0; i < 16; i++) { ulonglong2 v = p[i]; wn[2 * i] = v.x; wn[2 * i + 1] = v.y; }
    }
    float br = 0.f, bz = 0.f, bn = 0.f, gr = 0.f, gz = 0.f, gn = 0.f;
    float h_old = 0.f;
    if (!hf) {
        br = bhh[j]; bz = bhh[j + 128]; bn = bhh[j + 256];
        const float* gp = g_gi + (b * NTQ) * 384;
        gr = gp[j]; gz = gp[j + 128]; gn = gp[j + 256];
    }
    if (tid < 132) sbuf[0][tid] = 0.f;
    __syncthreads();

    for (int t = 0; t < NTQ; t++) {
        // prefetch next step's gi early (even lanes)
        float ngr = 0.f, ngz = 0.f, ngn = 0.f;
        if (!hf && t + 1 < NTQ) {
            const float* gp = g_gi + (b * NTQ + t + 1) * 384;
            ngr = gp[j]; ngz = gp[j + 128]; ngn = gp[j + 256];
        }
        const ulonglong2* h2 = (const ulonglong2*)(&sbuf[t & 1][hf * 68]);
        u64 ar0 = 0, ar1 = 0, az0 = 0, az1 = 0, an0 = 0, an1 = 0;
#pragma unroll
        for (int i = 0; i < 16; i++) {
            ulonglong2 hv = h2[i];
            ar0 = ffma2(wr[2 * i],     hv.x, ar0);
            ar1 = ffma2(wr[2 * i + 1], hv.y, ar1);
            az0 = ffma2(wz[2 * i],     hv.x, az0);
            az1 = ffma2(wz[2 * i + 1], hv.y, az1);
            an0 = ffma2(wn[2 * i],     hv.x, an0);
            an1 = ffma2(wn[2 * i + 1], hv.y, an1);
        }
        float pr = f2sum(fadd2(ar0, ar1));
        float pz = f2sum(fadd2(az0, az1));
        float pn = f2sum(fadd2(an0, an1));
        pr += __shfl_xor_sync(0xffffffffu, pr, 1);
        pz += __shfl_xor_sync(0xffffffffu, pz, 1);
        pn += __shfl_xor_sync(0xffffffffu, pn, 1);
        if (!hf) {
            float r = sigapx(pr + br + gr);
            float z = sigapx(pz + bz + gz);
            float n = tanhapx(fmaf(r, pn + bn, gn));
            h_old = fmaf(z, h_old - n, n);
            sbuf[(t + 1) & 1][(j < 64) ? j : (j + 4)] = h_old;
            gr = ngr; gz = ngz; gn = ngn;
        }
        __syncthreads();
    }
    if (!hf) g_hl[b * 128 + j] = h_old;
}

// ---------------------------------------------------------------------------
// Kernel 5: classifier MLP -> logits (B, 2)
// ---------------------------------------------------------------------------
__global__ __launch_bounds__(128) void k_cls(
    const float* __restrict__ c1w, const float* __restrict__ c1b,
    const float* __restrict__ c2w, const float* __restrict__ c2b,
    const float* __restrict__ c3w, const float* __restrict__ c3b,
    float* __restrict__ out)
{
    __shared__ float a[128];
    __shared__ float bb[128];
    const int tid = threadIdx.x;
    const int b = blockIdx.x;

    a[tid] = g_hl[b * 128 + tid];
    __syncthreads();
    {
        float acc = c1b[tid];
        const float4* wr = (const float4*)(c1w + tid * 128);
        const float4* h4 = (const float4*)a;
#pragma unroll
        for (int i = 0; i < 32; i++) {
            float4 wv = wr[i]; float4 hv = h4[i];
            acc += hv.x * wv.x + hv.y * wv.y + hv.z * wv.z + hv.w * wv.w;
        }
        bb[tid] = fmaxf(acc, 0.f);
    }
    __syncthreads();
    {
        float acc = c2b[tid];
        const float4* wr = (const float4*)(c2w + tid * 128);
        const float4* h4 = (const float4*)bb;
#pragma unroll
        for (int i = 0; i < 32; i++) {
            float4 wv = wr[i]; float4 hv = h4[i];
            acc += hv.x * wv.x + hv.y * wv.y + hv.z * wv.z + hv.w * wv.w;
        }
        a[tid] = fmaxf(acc, 0.f);
    }
    __syncthreads();
    if (tid < 32) {
        for (int s = 0; s < 2; s++) {
            float p = 0.f;
#pragma unroll
            for (int k = 0; k < 4; k++)
                p += a[tid + 32 * k] * c3w[s * 128 + tid + 32 * k];
            p = wsum(p);
            if (tid == 0) out[b * 2 + s] = p + c3b[s];
        }
    }
}

// ---------------------------------------------------------------------------
extern "C" void kernel_launch(void* const* d_in, const int* in_sizes, int n_in,
                              void* d_out, int out_size)
{
    const float* input      = (const float*)d_in[0];
    const float* mask       = (const float*)d_in[1];
    const float* timesteps  = (const float*)d_in[2];
    const float* periodic_w = (const float*)d_in[3];
    const float* periodic_b = (const float*)d_in[4];
    const float* lin_w      = (const float*)d_in[5];
    const float* lin_b      = (const float*)d_in[6];
    const float* q_w  = (const float*)d_in[7];
    const float* q_b  = (const float*)d_in[8];
    const float* q_g  = (const float*)d_in[9];
    const float* q_be = (const float*)d_in[10];
    const float* k_w  = (const float*)d_in[11];
    const float* k_b  = (const float*)d_in[12];
    const float* k_g  = (const float*)d_in[13];
    const float* k_be = (const float*)d_in[14];
    const float* attn_g = (const float*)d_in[15];
    const float* attn_b = (const float*)d_in[16];
    const float* out_w  = (const float*)d_in[17];
    const float* out_b  = (const float*)d_in[18];
    const float* out_g  = (const float*)d_in[19];
    const float* out_be = (const float*)d_in[20];
    const float* gru_wih = (const float*)d_in[21];
    const float* gru_whh = (const float*)d_in[22];
    const float* gru_bih = (const float*)d_in[23];
    const float* gru_bhh = (const float*)d_in[24];
    const float* c1_w = (const float*)d_in[25];
    const float* c1_b = (const float*)d_in[26];
    const float* c2_w = (const float*)d_in[27];
    const float* c2_b = (const float*)d_in[28];
    const float* c3_w = (const float*)d_in[29];
    const float* c3_b = (const float*)d_in[30];
    float* out = (float*)d_out;

    static bool attr_set = false;
    if (!attr_set) {
        cudaFuncSetAttribute(k_sattn, cudaFuncAttributeMaxDynamicSharedMemorySize, SATTN_SMEM);
        attr_set = true;
    }

    k_embed<<<132, 128>>>(timesteps, periodic_w, periodic_b, lin_w, lin_b,
                          q_w, q_b, q_g, q_be, k_w, k_b, k_g, k_be);
    k_sattn<<<128, 512, SATTN_SMEM>>>(input, mask);
    k_post<<<64, 384>>>(attn_g, attn_b, out_w, out_b, out_g, out_be,
                        gru_wih, gru_bih);
    k_gru<<<8, 256>>>(gru_whh, gru_bhh);
    k_cls<<<8, 128>>>(c1_w, c1_b, c2_w, c2_b, c3_w, c3_b, out);
    (void)in_sizes; (void)n_in; (void)out_size;
}